// round 1
// baseline (speedup 1.0000x reference)
#include <cuda_runtime.h>
#include <cuda_bf16.h>
#include <math.h>

// ---------------------------------------------------------------------------
// ResidualAttentionBlock: L=512, D=512, DC=256, T=128, FF=2048, P_COEF=0.5
//
// Pipeline:
//  1. ln1(x) -> x1 ; also build im2col Xt[(i*3+k)][h] = x1[i][2h+k-1]
//  2. q    = w_compress_k   @ Xt   (512x1536 @ 1536x256)
//     kcur = w_compress_cur @ Xt
//  3. flash kernel, grid (130,16):
//       bx==0   : self-attention (keys = q), full softmax -> g_self = A@q + q
//       bx=1..129: key-block kb=bx-1 (cached_k blocks 0..127, kcur = 128);
//                  masked blocks (mem_mask==0) return immediately;
//                  writes partial (m, l, acc) per (qtile, kb)
//  4. combine: merges partials + analytic contribution of n0 zero-keys
//              (logit 0 each), adds q and 0.5*self -> g_att
//  5. ap gemm  (+ap_b, +x1 resid) -> x2
//  6. ln2(x2) -> ln2buf
//  7. fc gemm  (+fc_b, silu(1.702)) -> h
//  8. proj gemm(+proj_b, +x2 resid) -> out
// ---------------------------------------------------------------------------

#define LL 512
#define DD 512
#define DC 256
#define TT 128
#define FF 2048

// scratch offsets (floats) in one big device buffer
#define O_X1   0
#define O_XT   (O_X1  + 512*512)        // 1536 x 256
#define O_Q    (O_XT  + 1536*256)
#define O_KC   (O_Q   + 512*256)
#define O_SELF (O_KC  + 512*256)
#define O_ATT  (O_SELF+ 512*256)
#define O_X2   (O_ATT + 512*256)
#define O_LN2  (O_X2  + 512*512)
#define O_H    (O_LN2 + 512*512)
#define O_PM   (O_H   + 512*2048)
#define O_PL   (O_PM  + 16*129*32)
#define O_PACC (O_PL  + 16*129*32)
#define BUF_TOTAL (O_PACC + 16*129*32*256)

__device__ float g_buf[BUF_TOTAL];

// ---------------------------------------------------------------------------
// LayerNorm over last dim (512). grid=512 rows, block=256.
// If xt != nullptr also emits im2col rows for the conv-GEMMs.
// ---------------------------------------------------------------------------
__global__ void ln_kernel(const float* __restrict__ in, const float* __restrict__ g,
                          const float* __restrict__ b, float* __restrict__ out,
                          float* __restrict__ xt) {
    __shared__ float row[512];
    __shared__ float sred[16];
    int l = blockIdx.x, t = threadIdx.x;
    float v0 = in[l*512 + t];
    float v1 = in[l*512 + 256 + t];
    float s = v0 + v1, sq = v0*v0 + v1*v1;
    #pragma unroll
    for (int o = 16; o; o >>= 1) {
        s  += __shfl_xor_sync(0xffffffffu, s,  o);
        sq += __shfl_xor_sync(0xffffffffu, sq, o);
    }
    if ((t & 31) == 0) { sred[t >> 5] = s; sred[8 + (t >> 5)] = sq; }
    __syncthreads();
    if (t == 0) {
        float a = 0.f, c = 0.f;
        #pragma unroll
        for (int i = 0; i < 8; i++) { a += sred[i]; c += sred[8+i]; }
        sred[0] = a; sred[8] = c;
    }
    __syncthreads();
    float mean = sred[0] * (1.f/512.f);
    float var  = sred[8] * (1.f/512.f) - mean*mean;
    float rstd = rsqrtf(var + 1e-5f);
    float y0 = (v0 - mean) * rstd * g[t]       + b[t];
    float y1 = (v1 - mean) * rstd * g[256 + t] + b[256 + t];
    out[l*512 + t]       = y0;
    out[l*512 + 256 + t] = y1;
    if (xt) {
        row[t] = y0; row[256 + t] = y1;
        __syncthreads();
        #pragma unroll
        for (int k = 0; k < 3; k++) {
            int idx = 2*t + k - 1;                 // in [-1, 511]
            float val = (idx >= 0) ? row[idx] : 0.f;
            xt[(l*3 + k)*256 + t] = val;
        }
    }
}

// ---------------------------------------------------------------------------
// Generic SGEMM: C[M,N] = A[M,K] @ B[K,N] (+bias) (+act) (+resid)
// 64x64 block tile, 256 threads (16x16), 4x4 per thread, K-chunk 16.
// M,N multiples of 64; K multiple of 16. act: 0=none, 1=silu(1.702)
// ---------------------------------------------------------------------------
__global__ void sgemm(const float* __restrict__ A, const float* __restrict__ B,
                      const float* __restrict__ bias, const float* __restrict__ resid,
                      float* __restrict__ C, int M, int N, int K, int act) {
    __shared__ float As[16][68];
    __shared__ float Bs[16][68];
    int tx = threadIdx.x, ty = threadIdx.y;
    int tid = ty*16 + tx;
    int m0 = blockIdx.y * 64, n0 = blockIdx.x * 64;
    int ar = tid >> 2, ac = (tid & 3) * 4;     // A tile: 64 rows x 16 k
    int br = tid >> 4, bc = (tid & 15) * 4;    // B tile: 16 k x 64 cols
    const float* Ap = A + (size_t)(m0 + ar)*K + ac;
    const float* Bp = B + (size_t)br*N + n0 + bc;
    float c[4][4] = {};
    for (int k0 = 0; k0 < K; k0 += 16) {
        float4 av = *(const float4*)(Ap + k0);
        float4 bv = *(const float4*)(Bp + (size_t)k0*N);
        __syncthreads();
        As[ac + 0][ar] = av.x;
        As[ac + 1][ar] = av.y;
        As[ac + 2][ar] = av.z;
        As[ac + 3][ar] = av.w;
        *(float4*)&Bs[br][bc] = bv;
        __syncthreads();
        #pragma unroll
        for (int kk = 0; kk < 16; kk++) {
            float4 a4 = *(const float4*)&As[kk][ty*4];
            float4 b4 = *(const float4*)&Bs[kk][tx*4];
            c[0][0] += a4.x*b4.x; c[0][1] += a4.x*b4.y; c[0][2] += a4.x*b4.z; c[0][3] += a4.x*b4.w;
            c[1][0] += a4.y*b4.x; c[1][1] += a4.y*b4.y; c[1][2] += a4.y*b4.z; c[1][3] += a4.y*b4.w;
            c[2][0] += a4.z*b4.x; c[2][1] += a4.z*b4.y; c[2][2] += a4.z*b4.z; c[2][3] += a4.z*b4.w;
            c[3][0] += a4.w*b4.x; c[3][1] += a4.w*b4.y; c[3][2] += a4.w*b4.z; c[3][3] += a4.w*b4.w;
        }
    }
    #pragma unroll
    for (int i = 0; i < 4; i++) {
        int mm = m0 + ty*4 + i;
        #pragma unroll
        for (int j = 0; j < 4; j++) {
            int nn = n0 + tx*4 + j;
            float v = c[i][j];
            if (bias)     v += bias[nn];
            if (act == 1) v = v / (1.f + __expf(-1.702f * v));
            if (resid)    v += resid[(size_t)mm*N + nn];
            C[(size_t)mm*N + nn] = v;
        }
    }
}

// ---------------------------------------------------------------------------
// Flash attention kernel. Block: 256 threads. Bq=32 queries, keys in
// subchunks of 32, D=256 (thread == dim in AV phase).
//   blockIdx.x == 0        -> self-attention mode (keys = q), writes g_self
//   blockIdx.x == 1..129   -> key-block kb = bx-1 (cached_k / kcur),
//                             writes partial (m, l, acc)
// q is pre-scaled by 1/sqrt(256) on load, so scores = dot(qs, k).
// Dynamic smem: qs[32][260] + ks[32][260] + st[32][36] + fb[32]
// ---------------------------------------------------------------------------
#define FL_SMEM_FLOATS (2*32*260 + 32*36 + 32)

__global__ void flash_kernel(const float* __restrict__ qg, const float* __restrict__ ck,
                             const float* __restrict__ kcur, const int* __restrict__ mask,
                             float* __restrict__ pm, float* __restrict__ pl,
                             float* __restrict__ pacc, float* __restrict__ selfout) {
    extern __shared__ float sm[];
    float* qs = sm;               // 32*260
    float* ks = sm + 32*260;      // 32*260
    float* st = sm + 2*32*260;    // st[j*36 + i]  (P^T, padded)
    float* fb = st + 32*36;       // 32 (rescale factors / final l)

    int tid = threadIdx.x;
    int qt  = blockIdx.y;
    int bx  = blockIdx.x;
    bool selfm = (bx == 0);
    int kbi = bx - 1;
    const float* kbase;
    if (selfm) {
        kbase = qg;
    } else {
        if (kbi < 128 && mask[kbi] == 0) return;   // zero rows: handled in combine
        kbase = (kbi < 128) ? ck + (size_t)kbi * 512 * 256 : kcur;
    }

    // load scaled q tile
    for (int i = tid; i < 32*256; i += 256) {
        int r = i >> 8, d = i & 255;
        qs[r*260 + d] = qg[(qt*32 + r)*256 + d] * 0.0625f;
    }

    float acc[32];
    #pragma unroll
    for (int i = 0; i < 32; i++) acc[i] = 0.f;
    float m = -1e30f, lsum = 0.f;   // meaningful in warp0 lanes (lane == query)

    int ti = tid >> 3;        // query index 0..31
    int tj = tid & 7;         // base key index; handles tj, tj+8, tj+16, tj+24

    for (int j0 = 0; j0 < 512; j0 += 32) {
        __syncthreads();      // protect ks from previous AV readers
        for (int i = tid; i < 32*256; i += 256) {
            int r = i >> 8, d = i & 255;
            ks[r*260 + d] = kbase[(size_t)(j0 + r)*256 + d];
        }
        __syncthreads();

        // ---- scores: S[32][32], 4 per thread ----
        {
            float s0 = 0.f, s1 = 0.f, s2 = 0.f, s3 = 0.f;
            const float4* q4  = (const float4*)(qs + ti*260);
            const float4* k0p = (const float4*)(ks + (tj     )*260);
            const float4* k1p = (const float4*)(ks + (tj +  8)*260);
            const float4* k2p = (const float4*)(ks + (tj + 16)*260);
            const float4* k3p = (const float4*)(ks + (tj + 24)*260);
            #pragma unroll 8
            for (int d4 = 0; d4 < 64; d4++) {
                float4 q = q4[d4];
                float4 a = k0p[d4];
                s0 += q.x*a.x + q.y*a.y + q.z*a.z + q.w*a.w;
                float4 b = k1p[d4];
                s1 += q.x*b.x + q.y*b.y + q.z*b.z + q.w*b.w;
                float4 cc = k2p[d4];
                s2 += q.x*cc.x + q.y*cc.y + q.z*cc.z + q.w*cc.w;
                float4 dd = k3p[d4];
                s3 += q.x*dd.x + q.y*dd.y + q.z*dd.z + q.w*dd.w;
            }
            st[(tj     )*36 + ti] = s0;
            st[(tj +  8)*36 + ti] = s1;
            st[(tj + 16)*36 + ti] = s2;
            st[(tj + 24)*36 + ti] = s3;
        }
        __syncthreads();

        // ---- online softmax update (warp0: lane r == query r) ----
        if (tid < 32) {
            int r = tid;
            float cm = -1e30f;
            #pragma unroll
            for (int j = 0; j < 32; j++) cm = fmaxf(cm, st[j*36 + r]);
            float mn = fmaxf(m, cm);
            float f  = __expf(m - mn);       // first chunk: exp(-huge) = 0
            float ls = 0.f;
            #pragma unroll
            for (int j = 0; j < 32; j++) {
                float p = __expf(st[j*36 + r] - mn);
                st[j*36 + r] = p;
                ls += p;
            }
            lsum = lsum * f + ls;
            m = mn;
            fb[r] = f;
        }
        __syncthreads();

        // ---- AV: thread owns dim d = tid for all 32 queries ----
        #pragma unroll
        for (int i = 0; i < 32; i++) acc[i] *= fb[i];
        for (int j = 0; j < 32; j++) {
            float kv = ks[j*260 + tid];
            const float4* p4 = (const float4*)(st + j*36);
            #pragma unroll
            for (int i4 = 0; i4 < 8; i4++) {
                float4 p = p4[i4];
                acc[4*i4 + 0] += p.x * kv;
                acc[4*i4 + 1] += p.y * kv;
                acc[4*i4 + 2] += p.z * kv;
                acc[4*i4 + 3] += p.w * kv;
            }
        }
    }

    if (selfm) {
        if (tid < 32) fb[tid] = lsum;
        __syncthreads();
        #pragma unroll
        for (int i = 0; i < 32; i++) {
            int qi = qt*32 + i;
            selfout[qi*256 + tid] = acc[i] / fb[i] + qg[qi*256 + tid];
        }
    } else {
        int base = (qt*129 + kbi)*32;
        if (tid < 32) { pm[base + tid] = m; pl[base + tid] = lsum; }
        #pragma unroll
        for (int i = 0; i < 32; i++)
            pacc[(size_t)(base + i)*256 + tid] = acc[i];
    }
}

// ---------------------------------------------------------------------------
// Combine partials: att = (sum acc*w)/(l_total) + q + 0.5*self
// Zero (masked) key blocks contribute 512 keys of logit 0 each.
// grid 512 (query), block 256 (dim).
// ---------------------------------------------------------------------------
__global__ void combine_kernel(const float* __restrict__ pm, const float* __restrict__ pl,
                               const float* __restrict__ pacc, const float* __restrict__ qg,
                               const float* __restrict__ selfv, const int* __restrict__ mask,
                               float* __restrict__ att) {
    int qi = blockIdx.x;
    int qt = qi >> 5, r = qi & 31;
    int d = threadIdx.x;
    float m = -1e30f;
    int nz = 0;
    for (int kb = 0; kb < 129; kb++) {
        if (kb == 128 || mask[kb] != 0)
            m = fmaxf(m, pm[(qt*129 + kb)*32 + r]);
        else
            nz++;
    }
    if (nz) m = fmaxf(m, 0.f);
    float l = nz ? (float)(nz * 512) * __expf(-m) : 0.f;
    float a = 0.f;
    for (int kb = 0; kb < 129; kb++) {
        if (kb == 128 || mask[kb] != 0) {
            int base = (qt*129 + kb)*32 + r;
            float w = __expf(pm[base] - m);
            l += pl[base] * w;
            a += pacc[(size_t)base*256 + d] * w;
        }
    }
    att[qi*256 + d] = a / l + qg[qi*256 + d] + 0.5f * selfv[qi*256 + d];
}

// ---------------------------------------------------------------------------
extern "C" void kernel_launch(void* const* d_in, const int* in_sizes, int n_in,
                              void* d_out, int out_size) {
    const float* x        = (const float*)d_in[0];
    const float* cached_k = (const float*)d_in[1];
    const float* ln1_g    = (const float*)d_in[2];
    const float* ln1_b    = (const float*)d_in[3];
    const float* ln2_g    = (const float*)d_in[4];
    const float* ln2_b    = (const float*)d_in[5];
    const float* wck      = (const float*)d_in[6];   // w_compress_k  -> q
    const float* wccur    = (const float*)d_in[7];   // w_compress_cur -> k_cur
    const float* ap_w     = (const float*)d_in[8];
    const float* ap_b     = (const float*)d_in[9];
    const float* fc_w     = (const float*)d_in[10];
    const float* fc_b     = (const float*)d_in[11];
    const float* proj_w   = (const float*)d_in[12];
    const float* proj_b   = (const float*)d_in[13];
    const int*   mask     = (const int*)d_in[14];
    float* out = (float*)d_out;

    float* base = nullptr;
    cudaGetSymbolAddress((void**)&base, g_buf);
    float* x1   = base + O_X1;
    float* xt   = base + O_XT;
    float* q    = base + O_Q;
    float* kc   = base + O_KC;
    float* self = base + O_SELF;
    float* att  = base + O_ATT;
    float* x2   = base + O_X2;
    float* ln2v = base + O_LN2;
    float* h    = base + O_H;
    float* pm   = base + O_PM;
    float* pl   = base + O_PL;
    float* pacc = base + O_PACC;

    // 1) ln1 + im2col
    ln_kernel<<<512, 256>>>(x, ln1_g, ln1_b, x1, xt);

    // 2) conv-as-GEMM: q and k_cur (M=512, N=256, K=1536)
    dim3 thr(16, 16);
    sgemm<<<dim3(256/64, 512/64), thr>>>(wck,   xt, nullptr, nullptr, q,  512, 256, 1536, 0);
    sgemm<<<dim3(256/64, 512/64), thr>>>(wccur, xt, nullptr, nullptr, kc, 512, 256, 1536, 0);

    // 3) flash attention (self + big partials)
    int fl_smem = FL_SMEM_FLOATS * (int)sizeof(float);
    cudaFuncSetAttribute(flash_kernel, cudaFuncAttributeMaxDynamicSharedMemorySize, fl_smem);
    flash_kernel<<<dim3(130, 16), 256, fl_smem>>>(q, cached_k, kc, mask, pm, pl, pacc, self);

    // 4) combine
    combine_kernel<<<512, 256>>>(pm, pl, pacc, q, self, mask, att);

    // 5) ap projection + residual(x1) -> x2   (M=512, N=512, K=256)
    sgemm<<<dim3(512/64, 512/64), thr>>>(att, ap_w, ap_b, x1, x2, 512, 512, 256, 0);

    // 6) ln2
    ln_kernel<<<512, 256>>>(x2, ln2_g, ln2_b, ln2v, nullptr);

    // 7) fc + silu(1.702)  (M=512, N=2048, K=512)
    sgemm<<<dim3(2048/64, 512/64), thr>>>(ln2v, fc_w, fc_b, nullptr, h, 512, 2048, 512, 1);

    // 8) proj + residual(x2) -> out  (M=512, N=512, K=2048)
    sgemm<<<dim3(512/64, 512/64), thr>>>(h, proj_w, proj_b, x2, out, 512, 512, 2048, 0);
}

// round 12
// speedup vs baseline: 1.9677x; 1.9677x over previous
#include <cuda_runtime.h>
#include <cuda_bf16.h>
#include <math.h>
#include <stdint.h>

// ---------------------------------------------------------------------------
// ResidualAttentionBlock L=512 D=512 DC=256 T=128 FF=2048, P_COEF=0.5
// R12 (= R8 resubmit; broker timeouts, never ran):
// tcgen05 unavailable (harness targets compute_103 -> ptxas rejects it).
// Flash attention via baseline-PTX mma.sync.m16n8k16 bf16 (HMMA) + ldmatrix.
// Split-V for precision, no-max softmax, partials+combine unchanged.
// ---------------------------------------------------------------------------

#define O_X1   0
#define O_XT   (O_X1  + 512*512)
#define O_Q    (O_XT  + 1536*256)
#define O_KC   (O_Q   + 512*256)
#define O_ATT  (O_KC  + 512*256)
#define O_X2   (O_ATT + 512*256)
#define O_LN2  (O_X2  + 512*512)
#define O_H    (O_LN2 + 512*512)
#define O_PL   (O_H   + 512*2048)
#define O_PACC (O_PL  + 130*512)
#define BUF_TOTAL (O_PACC + 130*512*256)

__device__ float g_buf[BUF_TOTAL];

// ---------------- helpers ----------------
__device__ __forceinline__ uint32_t smem_u32(const void* p) {
    uint32_t a;
    asm("{ .reg .u64 t; cvta.to.shared.u64 t, %1; cvt.u32.u64 %0, t; }" : "=r"(a) : "l"(p));
    return a;
}

#define LDSM_X4(r0,r1,r2,r3, addr) \
    asm volatile("ldmatrix.sync.aligned.m8n8.x4.shared.b16 {%0,%1,%2,%3}, [%4];" \
                 : "=r"(r0), "=r"(r1), "=r"(r2), "=r"(r3) : "r"(addr))
#define LDSM_X2(r0,r1, addr) \
    asm volatile("ldmatrix.sync.aligned.m8n8.x2.shared.b16 {%0,%1}, [%2];" \
                 : "=r"(r0), "=r"(r1) : "r"(addr))
#define LDSM_X4T(r0,r1,r2,r3, addr) \
    asm volatile("ldmatrix.sync.aligned.m8n8.x4.trans.shared.b16 {%0,%1,%2,%3}, [%4];" \
                 : "=r"(r0), "=r"(r1), "=r"(r2), "=r"(r3) : "r"(addr))
#define MMA16816(c, a0,a1,a2,a3, b0,b1) \
    asm volatile("mma.sync.aligned.m16n8k16.row.col.f32.bf16.bf16.f32 " \
                 "{%0,%1,%2,%3}, {%4,%5,%6,%7}, {%8,%9}, {%0,%1,%2,%3};" \
                 : "+f"((c)[0]), "+f"((c)[1]), "+f"((c)[2]), "+f"((c)[3]) \
                 : "r"(a0), "r"(a1), "r"(a2), "r"(a3), "r"(b0), "r"(b1))

#define SCALE_Q (0.0625f*1.44269504088896f)

// dynamic smem layout (bytes): Q 64x256 bf16 | Khi 128x256 | Klo 128x256 | P 64x128
#define SQ_OFF  0
#define SKH_OFF 32768
#define SKL_OFF 98304
#define SP_OFF  163840
#define FL_BYTES 180224

// ---------------------------------------------------------------------------
// flash_mma: one CTA per key-block kb (0..127 cached, 128 kcur, 129 self(q)).
// 256 threads (8 warps). qt loop: 8 tiles of 64 q; it loop: 4 iters of 128 keys.
// QK: warps = (q-strip 0..3) x (key-half 0..1). AV: warps = (q-strip) x (d-half).
// Writes unnormalized partials pl[kb][qi], pacc[kb][qi][d].
// ---------------------------------------------------------------------------
__global__ void __launch_bounds__(256, 1) flash_mma(
    const float* __restrict__ qg, const float* __restrict__ ck,
    const float* __restrict__ kc, const int* __restrict__ mask,
    float* __restrict__ pl, float* __restrict__ pacc)
{
    extern __shared__ char dyn[];
    __shared__ float lacc[64];
    __shared__ float ls2[2][64];
    uint32_t sbase = smem_u32(dyn);
    int tid = threadIdx.x, lane = tid & 31, wid = tid >> 5;
    int kb = blockIdx.x;

    const float* kbase;
    if (kb < 128) {
        if (mask[kb] == 0) return;
        kbase = ck + (size_t)kb * 512 * 256;
    } else if (kb == 128) kbase = kc;
    else kbase = qg;

    int strip = wid & 3;        // q-strip (16 rows) within 64-q tile
    int khalf = wid >> 2;       // key-half for QK / d-half for AV
    int gid = lane >> 2, tig = lane & 3;
    int sub = lane >> 3, r8 = lane & 7;
    int q0 = strip * 16;

    for (int qt = 0; qt < 8; qt++) {
        __syncthreads();               // staging region (Q/Khi) free again
        if (tid < 64) lacc[tid] = 0.f;

        // ---- load Q tile (64x256 fp32 -> scaled bf16, swizzled) ----
        #pragma unroll
        for (int i = 0; i < 8; i++) {
            int m = tid + i*256;
            int row = m >> 5, ch = m & 31;
            const float* src = qg + (size_t)(qt*64 + row)*256 + ch*8;
            float4 v0 = *(const float4*)src;
            float4 v1 = *(const float4*)(src + 4);
            __nv_bfloat162 c0 = __floats2bfloat162_rn(v0.x*SCALE_Q, v0.y*SCALE_Q);
            __nv_bfloat162 c1 = __floats2bfloat162_rn(v0.z*SCALE_Q, v0.w*SCALE_Q);
            __nv_bfloat162 c2 = __floats2bfloat162_rn(v1.x*SCALE_Q, v1.y*SCALE_Q);
            __nv_bfloat162 c3 = __floats2bfloat162_rn(v1.z*SCALE_Q, v1.w*SCALE_Q);
            uint4 pk = make_uint4(*(uint32_t*)&c0, *(uint32_t*)&c1,
                                  *(uint32_t*)&c2, *(uint32_t*)&c3);
            *(uint4*)(dyn + SQ_OFF + row*512 + ((ch ^ (row & 7)) << 4)) = pk;
        }

        float o[16][4];
        #pragma unroll
        for (int i = 0; i < 16; i++) { o[i][0]=0.f; o[i][1]=0.f; o[i][2]=0.f; o[i][3]=0.f; }

        for (int it = 0; it < 4; it++) {
            __syncthreads();
            // ---- load K/V tile (128x256), hi/lo bf16 split, swizzled ----
            #pragma unroll
            for (int i = 0; i < 16; i++) {
                int m = tid + i*256;
                int row = m >> 5, ch = m & 31;
                const float* src = kbase + (size_t)(it*128 + row)*256 + ch*8;
                float4 v0 = *(const float4*)src;
                float4 v1 = *(const float4*)(src + 4);
                __nv_bfloat16 h[8];
                h[0]=__float2bfloat16_rn(v0.x); h[1]=__float2bfloat16_rn(v0.y);
                h[2]=__float2bfloat16_rn(v0.z); h[3]=__float2bfloat16_rn(v0.w);
                h[4]=__float2bfloat16_rn(v1.x); h[5]=__float2bfloat16_rn(v1.y);
                h[6]=__float2bfloat16_rn(v1.z); h[7]=__float2bfloat16_rn(v1.w);
                __nv_bfloat162 l0 = __floats2bfloat162_rn(v0.x-__bfloat162float(h[0]), v0.y-__bfloat162float(h[1]));
                __nv_bfloat162 l1 = __floats2bfloat162_rn(v0.z-__bfloat162float(h[2]), v0.w-__bfloat162float(h[3]));
                __nv_bfloat162 l2 = __floats2bfloat162_rn(v1.x-__bfloat162float(h[4]), v1.y-__bfloat162float(h[5]));
                __nv_bfloat162 l3 = __floats2bfloat162_rn(v1.z-__bfloat162float(h[6]), v1.w-__bfloat162float(h[7]));
                uint32_t off = row*512 + ((ch ^ (row & 7)) << 4);
                __nv_bfloat162 h01 = __halves2bfloat162(h[0], h[1]);
                __nv_bfloat162 h23 = __halves2bfloat162(h[2], h[3]);
                __nv_bfloat162 h45 = __halves2bfloat162(h[4], h[5]);
                __nv_bfloat162 h67 = __halves2bfloat162(h[6], h[7]);
                *(uint4*)(dyn + SKH_OFF + off) = make_uint4(*(uint32_t*)&h01, *(uint32_t*)&h23,
                                                            *(uint32_t*)&h45, *(uint32_t*)&h67);
                *(uint4*)(dyn + SKL_OFF + off) = make_uint4(*(uint32_t*)&l0, *(uint32_t*)&l1,
                                                            *(uint32_t*)&l2, *(uint32_t*)&l3);
            }
            __syncthreads();

            // ---- QK^T: S[16q strip][64k half] ----
            float c[8][4];
            #pragma unroll
            for (int i = 0; i < 8; i++) { c[i][0]=0.f; c[i][1]=0.f; c[i][2]=0.f; c[i][3]=0.f; }
            for (int ks = 0; ks < 16; ks++) {
                int arow = q0 + r8 + (sub & 1)*8;
                int ach  = 2*ks + (sub >> 1);
                uint32_t aaddr = sbase + SQ_OFF + arow*512 + ((ach ^ (arow & 7)) << 4);
                uint32_t a0,a1,a2,a3;
                LDSM_X4(a0,a1,a2,a3, aaddr);
                #pragma unroll
                for (int nt = 0; nt < 8; nt++) {
                    int l16  = lane & 15;
                    int brow = khalf*64 + nt*8 + (l16 & 7);
                    int bch  = 2*ks + (l16 >> 3);
                    uint32_t baddr = sbase + SKH_OFF + brow*512 + ((bch ^ (brow & 7)) << 4);
                    uint32_t b0,b1;
                    LDSM_X2(b0,b1, baddr);
                    MMA16816(c[nt], a0,a1,a2,a3, b0,b1);
                }
            }

            // ---- epilogue: exp2, bf16 round, P->smem, row sums ----
            float rs0 = 0.f, rs1 = 0.f;
            #pragma unroll
            for (int nt = 0; nt < 8; nt++) {
                float p0 = exp2f(c[nt][0]), p1 = exp2f(c[nt][1]);
                float p2 = exp2f(c[nt][2]), p3 = exp2f(c[nt][3]);
                __nv_bfloat162 q01 = __floats2bfloat162_rn(p0, p1);
                __nv_bfloat162 q23 = __floats2bfloat162_rn(p2, p3);
                rs0 += __bfloat162float(__low2bfloat16(q01)) + __bfloat162float(__high2bfloat16(q01));
                rs1 += __bfloat162float(__low2bfloat16(q23)) + __bfloat162float(__high2bfloat16(q23));
                int key  = khalf*64 + nt*8 + 2*tig;
                int row0 = q0 + gid, row1 = row0 + 8;
                *(uint32_t*)(dyn + SP_OFF + row0*256 + (((key >> 3) ^ (row0 & 7)) << 4) + (key & 7)*2)
                    = *(uint32_t*)&q01;
                *(uint32_t*)(dyn + SP_OFF + row1*256 + (((key >> 3) ^ (row1 & 7)) << 4) + (key & 7)*2)
                    = *(uint32_t*)&q23;
            }
            rs0 += __shfl_xor_sync(0xffffffffu, rs0, 1);
            rs0 += __shfl_xor_sync(0xffffffffu, rs0, 2);
            rs1 += __shfl_xor_sync(0xffffffffu, rs1, 1);
            rs1 += __shfl_xor_sync(0xffffffffu, rs1, 2);
            if (tig == 0) {
                ls2[khalf][q0 + gid]     = rs0;
                ls2[khalf][q0 + gid + 8] = rs1;
            }
            __syncthreads();
            if (tid < 64) lacc[tid] += ls2[0][tid] + ls2[1][tid];

            // ---- AV: o[16q strip][128d half] += P @ (Vhi + Vlo) ----
            for (int ks = 0; ks < 8; ks++) {
                int arow = q0 + r8 + (sub & 1)*8;
                int ach  = 2*ks + (sub >> 1);
                uint32_t aaddr = sbase + SP_OFF + arow*256 + ((ach ^ (arow & 7)) << 4);
                uint32_t a0,a1,a2,a3;
                LDSM_X4(a0,a1,a2,a3, aaddr);
                #pragma unroll
                for (int hs = 0; hs < 2; hs++) {
                    uint32_t voff = hs ? SKL_OFF : SKH_OFF;
                    #pragma unroll
                    for (int np = 0; np < 8; np++) {
                        int vrow = 16*ks + r8 + (sub & 1)*8;
                        int vch  = khalf*16 + np*2 + (sub >> 1);
                        uint32_t baddr = sbase + voff + vrow*512 + ((vch ^ (vrow & 7)) << 4);
                        uint32_t b0,b1,b2,b3;
                        LDSM_X4T(b0,b1,b2,b3, baddr);
                        MMA16816(o[np*2],     a0,a1,a2,a3, b0,b1);
                        MMA16816(o[np*2 + 1], a0,a1,a2,a3, b2,b3);
                    }
                }
            }
        }

        // ---- write partials: stage acc via smem for coalesced gmem stores ----
        __syncthreads();                    // all AV reads of K tiles done
        float* stg = (float*)dyn;           // 64 x 260 fp32 (covers dead Q+Khi)
        #pragma unroll
        for (int nt = 0; nt < 16; nt++) {
            int d = khalf*128 + nt*8 + 2*tig;
            stg[(q0 + gid)*260 + d]       = o[nt][0];
            stg[(q0 + gid)*260 + d + 1]   = o[nt][1];
            stg[(q0 + gid + 8)*260 + d]   = o[nt][2];
            stg[(q0 + gid + 8)*260 + d+1] = o[nt][3];
        }
        __syncthreads();
        if (tid < 64) pl[kb*512 + qt*64 + tid] = lacc[tid];
        float* dst = pacc + ((size_t)kb*512 + qt*64)*256;
        #pragma unroll
        for (int e = 0; e < 16; e++) {
            int idx = tid*4 + e*1024;
            int row = idx >> 8, d = idx & 255;
            *(float4*)&dst[idx] = *(const float4*)&stg[row*260 + d];
        }
    }
}

// ---------------------------------------------------------------------------
// combine: att = a_big/l_big + 0.5*a_self/l_self + 1.5*q
// masked blocks contribute 512 keys of p=1 each (logit 0) to l_big.
// ---------------------------------------------------------------------------
__global__ void combine2(const float* __restrict__ pl, const float* __restrict__ pacc,
                         const float* __restrict__ qg, const int* __restrict__ mask,
                         float* __restrict__ att) {
    int qi = blockIdx.x, d = threadIdx.x;
    int nz = 0;
    float l = 0.f, a = 0.f;
    for (int kb = 0; kb < 129; kb++) {
        if (kb == 128 || mask[kb] != 0) {
            l += pl[kb*512 + qi];
            a += pacc[((size_t)kb*512 + qi)*256 + d];
        } else nz++;
    }
    l += 512.f * (float)nz;
    float ls = pl[129*512 + qi];
    float as_ = pacc[((size_t)129*512 + qi)*256 + d];
    float qv = qg[qi*256 + d];
    att[qi*256 + d] = a/l + 0.5f*as_/ls + 1.5f*qv;
}

// ---------------------------------------------------------------------------
// LayerNorm (unchanged R1)
// ---------------------------------------------------------------------------
__global__ void ln_kernel(const float* __restrict__ in, const float* __restrict__ g,
                          const float* __restrict__ b, float* __restrict__ out,
                          float* __restrict__ xt) {
    __shared__ float row[512];
    __shared__ float sred[16];
    int l = blockIdx.x, t = threadIdx.x;
    float v0 = in[l*512 + t];
    float v1 = in[l*512 + 256 + t];
    float s = v0 + v1, sq = v0*v0 + v1*v1;
    #pragma unroll
    for (int o = 16; o; o >>= 1) {
        s  += __shfl_xor_sync(0xffffffffu, s,  o);
        sq += __shfl_xor_sync(0xffffffffu, sq, o);
    }
    if ((t & 31) == 0) { sred[t >> 5] = s; sred[8 + (t >> 5)] = sq; }
    __syncthreads();
    if (t == 0) {
        float a = 0.f, c = 0.f;
        #pragma unroll
        for (int i = 0; i < 8; i++) { a += sred[i]; c += sred[8+i]; }
        sred[0] = a; sred[8] = c;
    }
    __syncthreads();
    float mean = sred[0] * (1.f/512.f);
    float var  = sred[8] * (1.f/512.f) - mean*mean;
    float rstd = rsqrtf(var + 1e-5f);
    float y0 = (v0 - mean) * rstd * g[t]       + b[t];
    float y1 = (v1 - mean) * rstd * g[256 + t] + b[256 + t];
    out[l*512 + t]       = y0;
    out[l*512 + 256 + t] = y1;
    if (xt) {
        row[t] = y0; row[256 + t] = y1;
        __syncthreads();
        #pragma unroll
        for (int k = 0; k < 3; k++) {
            int idx = 2*t + k - 1;
            float val = (idx >= 0) ? row[idx] : 0.f;
            xt[(l*3 + k)*256 + t] = val;
        }
    }
}

// ---------------------------------------------------------------------------
// SGEMM (unchanged R1)
// ---------------------------------------------------------------------------
__global__ void sgemm(const float* __restrict__ A, const float* __restrict__ B,
                      const float* __restrict__ bias, const float* __restrict__ resid,
                      float* __restrict__ C, int M, int N, int K, int act) {
    __shared__ float As[16][68];
    __shared__ float Bs[16][68];
    int tx = threadIdx.x, ty = threadIdx.y;
    int tid = ty*16 + tx;
    int m0 = blockIdx.y * 64, n0 = blockIdx.x * 64;
    int ar = tid >> 2, ac = (tid & 3) * 4;
    int br = tid >> 4, bc = (tid & 15) * 4;
    const float* Ap = A + (size_t)(m0 + ar)*K + ac;
    const float* Bp = B + (size_t)br*N + n0 + bc;
    float c[4][4] = {};
    for (int k0 = 0; k0 < K; k0 += 16) {
        float4 av = *(const float4*)(Ap + k0);
        float4 bv = *(const float4*)(Bp + (size_t)k0*N);
        __syncthreads();
        As[ac + 0][ar] = av.x;
        As[ac + 1][ar] = av.y;
        As[ac + 2][ar] = av.z;
        As[ac + 3][ar] = av.w;
        *(float4*)&Bs[br][bc] = bv;
        __syncthreads();
        #pragma unroll
        for (int kk = 0; kk < 16; kk++) {
            float4 a4 = *(const float4*)&As[kk][ty*4];
            float4 b4 = *(const float4*)&Bs[kk][tx*4];
            c[0][0] += a4.x*b4.x; c[0][1] += a4.x*b4.y; c[0][2] += a4.x*b4.z; c[0][3] += a4.x*b4.w;
            c[1][0] += a4.y*b4.x; c[1][1] += a4.y*b4.y; c[1][2] += a4.y*b4.z; c[1][3] += a4.y*b4.w;
            c[2][0] += a4.z*b4.x; c[2][1] += a4.z*b4.y; c[2][2] += a4.z*b4.z; c[2][3] += a4.z*b4.w;
            c[3][0] += a4.w*b4.x; c[3][1] += a4.w*b4.y; c[3][2] += a4.w*b4.z; c[3][3] += a4.w*b4.w;
        }
    }
    #pragma unroll
    for (int i = 0; i < 4; i++) {
        int mm = m0 + ty*4 + i;
        #pragma unroll
        for (int j = 0; j < 4; j++) {
            int nn = n0 + tx*4 + j;
            float v = c[i][j];
            if (bias)     v += bias[nn];
            if (act == 1) v = v / (1.f + __expf(-1.702f * v));
            if (resid)    v += resid[(size_t)mm*N + nn];
            C[(size_t)mm*N + nn] = v;
        }
    }
}

// ---------------------------------------------------------------------------
extern "C" void kernel_launch(void* const* d_in, const int* in_sizes, int n_in,
                              void* d_out, int out_size) {
    const float* x        = (const float*)d_in[0];
    const float* cached_k = (const float*)d_in[1];
    const float* ln1_g    = (const float*)d_in[2];
    const float* ln1_b    = (const float*)d_in[3];
    const float* ln2_g    = (const float*)d_in[4];
    const float* ln2_b    = (const float*)d_in[5];
    const float* wck      = (const float*)d_in[6];
    const float* wccur    = (const float*)d_in[7];
    const float* ap_w     = (const float*)d_in[8];
    const float* ap_b     = (const float*)d_in[9];
    const float* fc_w     = (const float*)d_in[10];
    const float* fc_b     = (const float*)d_in[11];
    const float* proj_w   = (const float*)d_in[12];
    const float* proj_b   = (const float*)d_in[13];
    const int*   mask     = (const int*)d_in[14];
    float* out = (float*)d_out;

    float* base = nullptr;
    cudaGetSymbolAddress((void**)&base, g_buf);
    float* x1   = base + O_X1;
    float* xt   = base + O_XT;
    float* q    = base + O_Q;
    float* kc   = base + O_KC;
    float* att  = base + O_ATT;
    float* x2   = base + O_X2;
    float* ln2v = base + O_LN2;
    float* h    = base + O_H;
    float* pl   = base + O_PL;
    float* pacc = base + O_PACC;

    // 1) ln1 + im2col
    ln_kernel<<<512, 256>>>(x, ln1_g, ln1_b, x1, xt);

    // 2) conv-as-GEMM: q and k_cur
    dim3 thr(16, 16);
    sgemm<<<dim3(256/64, 512/64), thr>>>(wck,   xt, nullptr, nullptr, q,  512, 256, 1536, 0);
    sgemm<<<dim3(256/64, 512/64), thr>>>(wccur, xt, nullptr, nullptr, kc, 512, 256, 1536, 0);

    // 3) HMMA flash attention (130 key-blocks incl. self)
    cudaFuncSetAttribute(flash_mma, cudaFuncAttributeMaxDynamicSharedMemorySize, FL_BYTES);
    flash_mma<<<130, 256, FL_BYTES>>>(q, cached_k, kc, mask, pl, pacc);

    // 4) combine
    combine2<<<512, 256>>>(pl, pacc, q, mask, att);

    // 5) ap projection + residual(x1) -> x2
    sgemm<<<dim3(512/64, 512/64), thr>>>(att, ap_w, ap_b, x1, x2, 512, 512, 256, 0);

    // 6) ln2
    ln_kernel<<<512, 256>>>(x2, ln2_g, ln2_b, ln2v, nullptr);

    // 7) fc + silu(1.702)
    sgemm<<<dim3(2048/64, 512/64), thr>>>(ln2v, fc_w, fc_b, nullptr, h, 512, 2048, 512, 1);

    // 8) proj + residual(x2) -> out
    sgemm<<<dim3(512/64, 512/64), thr>>>(h, proj_w, proj_b, x2, out, 512, 512, 2048, 0);
}